// round 4
// baseline (speedup 1.0000x reference)
#include <cuda_runtime.h>
#include <cuda_bf16.h>
#include <cstdint>

// Problem constants
#define BATCH 8192
#define CDIM  4096
#define FDIM  1024
#define ODIM  10

// Tile config
#define BM 128
#define BN 128
#define BK 32
#define BKP 40          // padded smem row length (elements) -> 80B rows, conflict-free frag loads
#define NCT (CDIM / BN) // 32 c-tiles
#define NBT (BATCH / BM)

// -------- scratch (device globals; allocation-free) --------
__device__ __nv_bfloat16 g_xb[(size_t)BATCH * FDIM];   // 16 MB
__device__ __nv_bfloat16 g_locb[(size_t)CDIM * FDIM];  //  8 MB
__device__ float g_x2[BATCH];
__device__ float g_c2[CDIM];
__device__ float g_invs[CDIM];
__device__ float g_partial[(size_t)NCT * BATCH * ODIM]; // ~10.5 MB

// ---------------- pre-pass: fp32 -> bf16 + row norms ----------------
// one block per row, 256 threads, 1024 cols -> 1 float4 per thread
__global__ void conv_x_kernel(const float* __restrict__ x) {
    int row = blockIdx.x;
    int tid = threadIdx.x;
    float4 v = ((const float4*)(x + (size_t)row * FDIM))[tid];
    float s = v.x * v.x + v.y * v.y + v.z * v.z + v.w * v.w;
    __nv_bfloat162* d = (__nv_bfloat162*)(g_xb + (size_t)row * FDIM);
    d[tid * 2 + 0] = __floats2bfloat162_rn(v.x, v.y);
    d[tid * 2 + 1] = __floats2bfloat162_rn(v.z, v.w);
    #pragma unroll
    for (int off = 16; off; off >>= 1) s += __shfl_xor_sync(0xffffffffu, s, off);
    __shared__ float wsum[8];
    if ((tid & 31) == 0) wsum[tid >> 5] = s;
    __syncthreads();
    if (tid == 0) {
        float t = 0.f;
        #pragma unroll
        for (int i = 0; i < 8; i++) t += wsum[i];
        g_x2[row] = t;
    }
}

__global__ void conv_loc_kernel(const float* __restrict__ loc) {
    int row = blockIdx.x;
    int tid = threadIdx.x;
    float4 v = ((const float4*)(loc + (size_t)row * FDIM))[tid];
    float s = v.x * v.x + v.y * v.y + v.z * v.z + v.w * v.w;
    __nv_bfloat162* d = (__nv_bfloat162*)(g_locb + (size_t)row * FDIM);
    d[tid * 2 + 0] = __floats2bfloat162_rn(v.x, v.y);
    d[tid * 2 + 1] = __floats2bfloat162_rn(v.z, v.w);
    #pragma unroll
    for (int off = 16; off; off >>= 1) s += __shfl_xor_sync(0xffffffffu, s, off);
    __shared__ float wsum[8];
    if ((tid & 31) == 0) wsum[tid >> 5] = s;
    __syncthreads();
    if (tid == 0) {
        float t = 0.f;
        #pragma unroll
        for (int i = 0; i < 8; i++) t += wsum[i];
        g_c2[row] = t;
    }
}

__global__ void invs_kernel(const float* __restrict__ scale) {
    int i = blockIdx.x * 256 + threadIdx.x;
    if (i < CDIM) g_invs[i] = 1.0f / scale[i];
}

// ---------------- main fused kernel ----------------
// CTA = (b_tile, c_tile) 128x128. 8 warps as 4(m) x 2(n): warp tile 32x64.
// mma.sync.aligned.m16n8k16 bf16 -> fp32 acc. Epilogue fused: sqrt/exp + w projection.
__device__ __forceinline__ void mma_bf16(float c[4], const uint32_t a[4], const uint32_t b[2]) {
    asm volatile(
        "mma.sync.aligned.m16n8k16.row.col.f32.bf16.bf16.f32 "
        "{%0,%1,%2,%3}, {%4,%5,%6,%7}, {%8,%9}, {%0,%1,%2,%3};\n"
        : "+f"(c[0]), "+f"(c[1]), "+f"(c[2]), "+f"(c[3])
        : "r"(a[0]), "r"(a[1]), "r"(a[2]), "r"(a[3]),
          "r"(b[0]), "r"(b[1]));
}

__global__ __launch_bounds__(256, 2)
void rbf_main_kernel(const float* __restrict__ w) {
    __shared__ __nv_bfloat16 As[BM][BKP];
    __shared__ __nv_bfloat16 Bs[BN][BKP];
    __shared__ float wsm[ODIM][BN];
    __shared__ float sout[BM][ODIM];
    __shared__ float x2s[BM];
    __shared__ float c2s[BN];
    __shared__ float ivs[BN];

    const int bt = blockIdx.x;  // 0..63
    const int ct = blockIdx.y;  // 0..31
    const int tid = threadIdx.x;
    const int lane = tid & 31;
    const int warp = tid >> 5;
    const int wm = warp & 3;    // m offset wm*32
    const int wn = warp >> 2;   // n offset wn*64

    // init sout, load w tile + norms + inv scales
    for (int i = tid; i < BM * ODIM; i += 256) ((float*)sout)[i] = 0.f;
    for (int i = tid; i < ODIM * BN; i += 256) {
        int o = i / BN, c = i % BN;
        wsm[o][c] = w[(size_t)o * CDIM + ct * BN + c];
    }
    if (tid < BN) { c2s[tid] = g_c2[ct * BN + tid]; ivs[tid] = g_invs[ct * BN + tid]; }
    if (tid < BM) { x2s[tid] = g_x2[bt * BM + tid]; }

    float acc[2][8][4];
    #pragma unroll
    for (int mi = 0; mi < 2; mi++)
        #pragma unroll
        for (int ni = 0; ni < 8; ni++)
            #pragma unroll
            for (int e = 0; e < 4; e++) acc[mi][ni][e] = 0.f;

    const int lr = lane >> 2;         // 0..7
    const int lc = (lane & 3) * 2;    // 0,2,4,6

    for (int k0 = 0; k0 < FDIM; k0 += BK) {
        __syncthreads();  // protect previous iteration's reads (and first-iter smem init)
        // load A tile: 128 rows x 32 bf16 = 512 x uint4
        #pragma unroll
        for (int i = 0; i < 2; i++) {
            int idx = tid + i * 256;
            int r = idx >> 2, ch = idx & 3;
            uint4 v = *(const uint4*)(g_xb + ((size_t)(bt * BM + r)) * FDIM + k0 + ch * 8);
            *(uint4*)(&As[r][ch * 8]) = v;
        }
        // load B tile (loc)
        #pragma unroll
        for (int i = 0; i < 2; i++) {
            int idx = tid + i * 256;
            int r = idx >> 2, ch = idx & 3;
            uint4 v = *(const uint4*)(g_locb + ((size_t)(ct * BN + r)) * FDIM + k0 + ch * 8);
            *(uint4*)(&Bs[r][ch * 8]) = v;
        }
        __syncthreads();

        #pragma unroll
        for (int ks = 0; ks < BK; ks += 16) {
            uint32_t afr[2][4];
            uint32_t bfr[8][2];
            #pragma unroll
            for (int mi = 0; mi < 2; mi++) {
                int r0 = wm * 32 + mi * 16 + lr;
                afr[mi][0] = *(const uint32_t*)(&As[r0    ][ks + lc    ]);
                afr[mi][1] = *(const uint32_t*)(&As[r0 + 8][ks + lc    ]);
                afr[mi][2] = *(const uint32_t*)(&As[r0    ][ks + lc + 8]);
                afr[mi][3] = *(const uint32_t*)(&As[r0 + 8][ks + lc + 8]);
            }
            #pragma unroll
            for (int ni = 0; ni < 8; ni++) {
                int rn = wn * 64 + ni * 8 + lr;
                bfr[ni][0] = *(const uint32_t*)(&Bs[rn][ks + lc    ]);
                bfr[ni][1] = *(const uint32_t*)(&Bs[rn][ks + lc + 8]);
            }
            #pragma unroll
            for (int mi = 0; mi < 2; mi++)
                #pragma unroll
                for (int ni = 0; ni < 8; ni++)
                    mma_bf16(acc[mi][ni], afr[mi], bfr[ni]);
        }
    }
    __syncthreads();

    // Fused epilogue: phi = exp(-sqrt(max(x2+c2-2*dot,0))/scale); project onto w rows.
    #pragma unroll
    for (int mi = 0; mi < 2; mi++) {
        float p0[ODIM], p1[ODIM];
        #pragma unroll
        for (int o = 0; o < ODIM; o++) { p0[o] = 0.f; p1[o] = 0.f; }
        const int r0 = wm * 32 + mi * 16 + lr;   // local row; r1 = r0+8
        const float xx0 = x2s[r0];
        const float xx1 = x2s[r0 + 8];
        #pragma unroll
        for (int ni = 0; ni < 8; ni++) {
            #pragma unroll
            for (int j = 0; j < 2; j++) {
                const int cl = wn * 64 + ni * 8 + lc + j;
                const float cc = c2s[cl];
                const float iv = ivs[cl];
                const float s0 = acc[mi][ni][j];
                const float s1 = acc[mi][ni][2 + j];
                const float d0 = sqrtf(fmaxf(xx0 + cc - 2.0f * s0, 0.f));
                const float d1 = sqrtf(fmaxf(xx1 + cc - 2.0f * s1, 0.f));
                const float ph0 = __expf(-d0 * iv);
                const float ph1 = __expf(-d1 * iv);
                #pragma unroll
                for (int o = 0; o < ODIM; o++) {
                    const float wv = wsm[o][cl];
                    p0[o] = fmaf(ph0, wv, p0[o]);
                    p1[o] = fmaf(ph1, wv, p1[o]);
                }
            }
        }
        // reduce across the 4 lanes sharing a row (lane&3 group)
        #pragma unroll
        for (int o = 0; o < ODIM; o++) {
            p0[o] += __shfl_xor_sync(0xffffffffu, p0[o], 1);
            p0[o] += __shfl_xor_sync(0xffffffffu, p0[o], 2);
            p1[o] += __shfl_xor_sync(0xffffffffu, p1[o], 1);
            p1[o] += __shfl_xor_sync(0xffffffffu, p1[o], 2);
        }
        if ((lane & 3) == 0) {
            // exactly 2 contributors per cell (wn=0,1): float add is commutative -> deterministic
            #pragma unroll
            for (int o = 0; o < ODIM; o++) {
                atomicAdd(&sout[r0][o], p0[o]);
                atomicAdd(&sout[r0 + 8][o], p1[o]);
            }
        }
    }
    __syncthreads();

    // write deterministic per-c-tile partials
    for (int i = tid; i < BM * ODIM; i += 256) {
        int r = i / ODIM, o = i % ODIM;
        g_partial[(size_t)ct * (BATCH * ODIM) + (size_t)(bt * BM + r) * ODIM + o] = sout[r][o];
    }
}

// ---------------- final reduce over c-tiles ----------------
__global__ void reduce_out_kernel(float* __restrict__ out) {
    int i = blockIdx.x * 256 + threadIdx.x;
    if (i < BATCH * ODIM) {
        float s = 0.f;
        #pragma unroll
        for (int ctl = 0; ctl < NCT; ctl++) s += g_partial[(size_t)ctl * (BATCH * ODIM) + i];
        out[i] = s;
    }
}

// ---------------- launcher ----------------
extern "C" void kernel_launch(void* const* d_in, const int* in_sizes, int n_in,
                              void* d_out, int out_size) {
    const float* x     = (const float*)d_in[0];  // [8192,1024]
    const float* loc   = (const float*)d_in[1];  // [4096,1024]
    const float* scale = (const float*)d_in[2];  // [4096]
    const float* w     = (const float*)d_in[3];  // [10,4096]
    float* out = (float*)d_out;                  // [8192,10]

    conv_x_kernel<<<BATCH, 256>>>(x);
    conv_loc_kernel<<<CDIM, 256>>>(loc);
    invs_kernel<<<(CDIM + 255) / 256, 256>>>(scale);

    dim3 grid(NBT, NCT);
    rbf_main_kernel<<<grid, 256>>>(w);

    reduce_out_kernel<<<(BATCH * ODIM + 255) / 256, 256>>>(out);
}

// round 10
// speedup vs baseline: 1.3433x; 1.3433x over previous
#include <cuda_runtime.h>
#include <cuda_bf16.h>
#include <cstdint>

// ---------------- problem constants ----------------
#define BATCH 8192
#define CDIM  4096
#define FDIM  1024
#define ODIM  10

// ---------------- tile config ----------------
#define BM 128
#define BN 128
#define BK 64                 // bf16 elements per K chunk (= 128 bytes per row)
#define KSTEPS (FDIM / BK)    // 16 chunks
#define NCT (CDIM / BN)       // 32 c-tiles
#define NBT (BATCH / BM)      // 64 b-tiles

// ---------------- smem layout (bytes, dynamic) ----------------
// per buffer: A 128x128B = 16KB, B 128x128B = 16KB
#define SM_ABUF(b)  ((b) * 32768)
#define SM_BBUF(b)  ((b) * 32768 + 16384)
#define SM_WPACK    65536                   // float [128][12]  (w repacked, padded)
#define SM_C2IV     (SM_WPACK + 6144)       // float2 [128] (c2, 1/scale)
#define SM_X2       (SM_C2IV + 1024)        // float  [128]
#define SMEM_TOTAL  (SM_X2 + 512)           // 73216 B -> 2 CTAs/SM
// sout (float[128][10]) reuses the dead A0 buffer after the mainloop.

// -------- scratch (device globals; allocation-free) --------
__device__ __nv_bfloat16 g_xb[(size_t)BATCH * FDIM];   // 16 MB
__device__ __nv_bfloat16 g_locb[(size_t)CDIM * FDIM];  //  8 MB
__device__ float g_x2[BATCH];
__device__ float g_c2[CDIM];
__device__ float g_invs[CDIM];
__device__ float g_partial[(size_t)NCT * BATCH * ODIM]; // 10.5 MB

// ---------------- PTX helpers ----------------
__device__ __forceinline__ uint32_t smem_u32(const void* p) {
    uint32_t a;
    asm("{ .reg .u64 t; cvta.to.shared.u64 t, %1; cvt.u32.u64 %0, t; }" : "=r"(a) : "l"(p));
    return a;
}
__device__ __forceinline__ void cp16(uint32_t dst, const void* src) {
    asm volatile("cp.async.cg.shared.global [%0], [%1], 16;" :: "r"(dst), "l"(src));
}
#define CP_COMMIT() asm volatile("cp.async.commit_group;" ::: "memory")
#define CP_WAIT1()  asm volatile("cp.async.wait_group 1;" ::: "memory")

#define LDSM4(r0, r1, r2, r3, addr) \
    asm volatile("ldmatrix.sync.aligned.m8n8.x4.shared.b16 {%0,%1,%2,%3}, [%4];" \
                 : "=r"(r0), "=r"(r1), "=r"(r2), "=r"(r3) : "r"(addr))

__device__ __forceinline__ void mma_bf16(float c[4], const uint32_t a[4],
                                         uint32_t b0, uint32_t b1) {
    asm volatile(
        "mma.sync.aligned.m16n8k16.row.col.f32.bf16.bf16.f32 "
        "{%0,%1,%2,%3}, {%4,%5,%6,%7}, {%8,%9}, {%0,%1,%2,%3};\n"
        : "+f"(c[0]), "+f"(c[1]), "+f"(c[2]), "+f"(c[3])
        : "r"(a[0]), "r"(a[1]), "r"(a[2]), "r"(a[3]), "r"(b0), "r"(b1));
}

// ---------------- pre-pass: fp32 -> bf16 + row norms ----------------
__global__ void conv_x_kernel(const float* __restrict__ x) {
    int row = blockIdx.x, tid = threadIdx.x;
    float4 v = ((const float4*)(x + (size_t)row * FDIM))[tid];
    float s = v.x * v.x + v.y * v.y + v.z * v.z + v.w * v.w;
    __nv_bfloat162* d = (__nv_bfloat162*)(g_xb + (size_t)row * FDIM);
    d[tid * 2 + 0] = __floats2bfloat162_rn(v.x, v.y);
    d[tid * 2 + 1] = __floats2bfloat162_rn(v.z, v.w);
    #pragma unroll
    for (int off = 16; off; off >>= 1) s += __shfl_xor_sync(0xffffffffu, s, off);
    __shared__ float wsum[8];
    if ((tid & 31) == 0) wsum[tid >> 5] = s;
    __syncthreads();
    if (tid == 0) {
        float t = 0.f;
        #pragma unroll
        for (int i = 0; i < 8; i++) t += wsum[i];
        g_x2[row] = t;
    }
}

__global__ void conv_loc_kernel(const float* __restrict__ loc) {
    int row = blockIdx.x, tid = threadIdx.x;
    float4 v = ((const float4*)(loc + (size_t)row * FDIM))[tid];
    float s = v.x * v.x + v.y * v.y + v.z * v.z + v.w * v.w;
    __nv_bfloat162* d = (__nv_bfloat162*)(g_locb + (size_t)row * FDIM);
    d[tid * 2 + 0] = __floats2bfloat162_rn(v.x, v.y);
    d[tid * 2 + 1] = __floats2bfloat162_rn(v.z, v.w);
    #pragma unroll
    for (int off = 16; off; off >>= 1) s += __shfl_xor_sync(0xffffffffu, s, off);
    __shared__ float wsum[8];
    if ((tid & 31) == 0) wsum[tid >> 5] = s;
    __syncthreads();
    if (tid == 0) {
        float t = 0.f;
        #pragma unroll
        for (int i = 0; i < 8; i++) t += wsum[i];
        g_c2[row] = t;
    }
}

__global__ void invs_kernel(const float* __restrict__ scale) {
    int i = blockIdx.x * 256 + threadIdx.x;
    if (i < CDIM) g_invs[i] = 1.0f / scale[i];
}

// ---------------- tile loader: cp.async with swizzle ----------------
// 128B rows; swizzle: chunk' = chunk ^ (row&7)  (16B chunks)
__device__ __forceinline__ void load_tile(uint32_t sbase, int buf, int k0,
                                          int bt, int ct, int tid) {
    const __nv_bfloat16* ga = g_xb + ((size_t)bt * BM) * FDIM + k0;
    uint32_t adst = sbase + SM_ABUF(buf);
    #pragma unroll
    for (int i = 0; i < 4; i++) {            // 128 rows x 8 x 16B chunks
        int idx = tid + i * 256;
        int r = idx >> 3, c = idx & 7;
        uint32_t sw = ((uint32_t)r << 7) | ((uint32_t)(c ^ (r & 7)) << 4);
        cp16(adst + sw, ga + (size_t)r * FDIM + c * 8);
    }
    const __nv_bfloat16* gb = g_locb + ((size_t)ct * BN) * FDIM + k0;
    uint32_t bdst = sbase + SM_BBUF(buf);
    #pragma unroll
    for (int i = 0; i < 4; i++) {            // 128 rows x 8 x 16B chunks
        int idx = tid + i * 256;
        int r = idx >> 3, c = idx & 7;
        uint32_t sw = ((uint32_t)r << 7) | ((uint32_t)(c ^ (r & 7)) << 4);
        cp16(bdst + sw, gb + (size_t)r * FDIM + c * 8);
    }
}

// ---------------- main fused kernel: mma.sync + ldmatrix + cp.async ----------------
// CTA = 128x128 tile. 8 warps as 4(m) x 2(n): warp tile 32x64.
__global__ __launch_bounds__(256, 2)
void rbf_main_kernel(const float* __restrict__ w) {
    extern __shared__ char smem[];
    const uint32_t sbase = smem_u32(smem);
    const int tid = threadIdx.x;
    const int lane = tid & 31;
    const int warp = tid >> 5;
    const int wm = warp & 3;    // m offset wm*32
    const int wn = warp >> 2;   // n offset wn*64
    const int bt = blockIdx.x;
    const int ct = blockIdx.y;

    // stage epilogue params into smem
    float*  wpack = (float*)(smem + SM_WPACK);   // [128][12]
    float2* c2iv  = (float2*)(smem + SM_C2IV);   // [128]
    float*  x2s   = (float*)(smem + SM_X2);      // [128]
    for (int i = tid; i < BN * ODIM; i += 256) {
        int c = i / ODIM, o = i % ODIM;
        wpack[c * 12 + o] = w[(size_t)o * CDIM + ct * BN + c];
    }
    if (tid < BN) c2iv[tid] = make_float2(g_c2[ct * BN + tid], g_invs[ct * BN + tid]);
    if (tid < BM) x2s[tid] = g_x2[bt * BM + tid];

    // prologue: prefetch chunks 0 and 1
    load_tile(sbase, 0, 0 * BK, bt, ct, tid);
    CP_COMMIT();
    load_tile(sbase, 1, 1 * BK, bt, ct, tid);
    CP_COMMIT();

    // per-lane ldmatrix base offsets (ks=0); K-step advance is XOR (ks<<5)
    // base chunk bit0 = (mat>>1); swizzled base chunk = (mat>>1) ^ (row&7)
    const int mat = lane >> 3, rin = lane & 7;
    uint32_t aoff[2], boff[4];
    #pragma unroll
    for (int mi = 0; mi < 2; mi++) {
        int row = wm * 32 + mi * 16 + (mat & 1) * 8 + rin;
        aoff[mi] = ((uint32_t)row << 7) | ((uint32_t)((mat >> 1) ^ (row & 7)) << 4);
    }
    #pragma unroll
    for (int ni2 = 0; ni2 < 4; ni2++) {
        int row = wn * 64 + ni2 * 16 + (mat & 1) * 8 + rin;
        boff[ni2] = ((uint32_t)row << 7) | ((uint32_t)((mat >> 1) ^ (row & 7)) << 4);
    }

    float acc[2][8][4];
    #pragma unroll
    for (int mi = 0; mi < 2; mi++)
        #pragma unroll
        for (int ni = 0; ni < 8; ni++)
            #pragma unroll
            for (int e = 0; e < 4; e++) acc[mi][ni][e] = 0.f;

    // ---------------- K mainloop (double-buffered) ----------------
    for (int s = 0; s < KSTEPS; s++) {
        const int buf = s & 1;
        CP_WAIT1();          // chunk s resident for this thread
        __syncthreads();     // ... and for all threads

        const uint32_t abase = sbase + SM_ABUF(buf);
        const uint32_t bbase = sbase + SM_BBUF(buf);
        #pragma unroll
        for (int ks = 0; ks < BK / 16; ks++) {
            uint32_t a[2][4], b[4][4];
            #pragma unroll
            for (int mi = 0; mi < 2; mi++)
                LDSM4(a[mi][0], a[mi][1], a[mi][2], a[mi][3],
                      abase + (aoff[mi] ^ ((uint32_t)ks << 5)));   // XOR, not add!
            #pragma unroll
            for (int ni2 = 0; ni2 < 4; ni2++)
                LDSM4(b[ni2][0], b[ni2][1], b[ni2][2], b[ni2][3],
                      bbase + (boff[ni2] ^ ((uint32_t)ks << 5)));  // XOR, not add!
            #pragma unroll
            for (int mi = 0; mi < 2; mi++)
                #pragma unroll
                for (int ni2 = 0; ni2 < 4; ni2++) {
                    mma_bf16(acc[mi][ni2 * 2 + 0], a[mi], b[ni2][0], b[ni2][2]);
                    mma_bf16(acc[mi][ni2 * 2 + 1], a[mi], b[ni2][1], b[ni2][3]);
                }
        }
        __syncthreads();     // all warps done reading buf before overwrite

        if (s + 2 < KSTEPS) load_tile(sbase, buf, (s + 2) * BK, bt, ct, tid);
        CP_COMMIT();         // exactly one group per iteration (maybe empty)
    }

    // zero sout (aliases dead A0 buffer)
    float* sout = (float*)smem;   // [128][10]
    for (int i = tid; i < BM * ODIM; i += 256) sout[i] = 0.f;
    __syncthreads();

    // ---------------- fused epilogue ----------------
    const int lr = lane >> 2;         // 0..7
    const int lc = (lane & 3) * 2;    // 0,2,4,6
    #pragma unroll
    for (int mi = 0; mi < 2; mi++) {
        float p0[ODIM], p1[ODIM];
        #pragma unroll
        for (int o = 0; o < ODIM; o++) { p0[o] = 0.f; p1[o] = 0.f; }
        const int r0 = wm * 32 + mi * 16 + lr;   // local row; r1 = r0+8
        const float xx0 = x2s[r0];
        const float xx1 = x2s[r0 + 8];
        #pragma unroll
        for (int ni = 0; ni < 8; ni++) {
            #pragma unroll
            for (int j = 0; j < 2; j++) {
                const int cl = wn * 64 + ni * 8 + lc + j;
                const float2 ci = c2iv[cl];
                const float s0 = acc[mi][ni][j];
                const float s1 = acc[mi][ni][2 + j];
                const float d0 = sqrtf(fmaxf(fmaf(-2.0f, s0, xx0 + ci.x), 0.f));
                const float d1 = sqrtf(fmaxf(fmaf(-2.0f, s1, xx1 + ci.x), 0.f));
                const float ph0 = __expf(-d0 * ci.y);
                const float ph1 = __expf(-d1 * ci.y);
                const float4 w0 = *(const float4*)&wpack[cl * 12];
                const float4 w1 = *(const float4*)&wpack[cl * 12 + 4];
                const float2 w2 = *(const float2*)&wpack[cl * 12 + 8];
                p0[0] = fmaf(ph0, w0.x, p0[0]);  p1[0] = fmaf(ph1, w0.x, p1[0]);
                p0[1] = fmaf(ph0, w0.y, p0[1]);  p1[1] = fmaf(ph1, w0.y, p1[1]);
                p0[2] = fmaf(ph0, w0.z, p0[2]);  p1[2] = fmaf(ph1, w0.z, p1[2]);
                p0[3] = fmaf(ph0, w0.w, p0[3]);  p1[3] = fmaf(ph1, w0.w, p1[3]);
                p0[4] = fmaf(ph0, w1.x, p0[4]);  p1[4] = fmaf(ph1, w1.x, p1[4]);
                p0[5] = fmaf(ph0, w1.y, p0[5]);  p1[5] = fmaf(ph1, w1.y, p1[5]);
                p0[6] = fmaf(ph0, w1.z, p0[6]);  p1[6] = fmaf(ph1, w1.z, p1[6]);
                p0[7] = fmaf(ph0, w1.w, p0[7]);  p1[7] = fmaf(ph1, w1.w, p1[7]);
                p0[8] = fmaf(ph0, w2.x, p0[8]);  p1[8] = fmaf(ph1, w2.x, p1[8]);
                p0[9] = fmaf(ph0, w2.y, p0[9]);  p1[9] = fmaf(ph1, w2.y, p1[9]);
            }
        }
        // reduce across the 4 lanes sharing a row
        #pragma unroll
        for (int o = 0; o < ODIM; o++) {
            p0[o] += __shfl_xor_sync(0xffffffffu, p0[o], 1);
            p0[o] += __shfl_xor_sync(0xffffffffu, p0[o], 2);
            p1[o] += __shfl_xor_sync(0xffffffffu, p1[o], 1);
            p1[o] += __shfl_xor_sync(0xffffffffu, p1[o], 2);
        }
        if ((lane & 3) == 0) {
            // exactly 2 contributors per cell (wn=0,1): commutative -> deterministic
            #pragma unroll
            for (int o = 0; o < ODIM; o++) {
                atomicAdd(&sout[r0 * ODIM + o], p0[o]);
                atomicAdd(&sout[(r0 + 8) * ODIM + o], p1[o]);
            }
        }
    }
    __syncthreads();

    // write deterministic per-c-tile partials
    for (int i = tid; i < BM * ODIM; i += 256) {
        int r = i / ODIM, o = i % ODIM;
        g_partial[(size_t)ct * (BATCH * ODIM) + (size_t)(bt * BM + r) * ODIM + o] = sout[i];
    }
}

// ---------------- final reduce over c-tiles ----------------
__global__ void reduce_out_kernel(float* __restrict__ out) {
    int i = blockIdx.x * 256 + threadIdx.x;
    if (i < BATCH * ODIM) {
        float s = 0.f;
        #pragma unroll
        for (int ctl = 0; ctl < NCT; ctl++) s += g_partial[(size_t)ctl * (BATCH * ODIM) + i];
        out[i] = s;
    }
}

// ---------------- launcher ----------------
extern "C" void kernel_launch(void* const* d_in, const int* in_sizes, int n_in,
                              void* d_out, int out_size) {
    const float* x     = (const float*)d_in[0];  // [8192,1024]
    const float* loc   = (const float*)d_in[1];  // [4096,1024]
    const float* scale = (const float*)d_in[2];  // [4096]
    const float* w     = (const float*)d_in[3];  // [10,4096]
    float* out = (float*)d_out;                  // [8192,10]

    cudaFuncSetAttribute(rbf_main_kernel,
                         cudaFuncAttributeMaxDynamicSharedMemorySize, SMEM_TOTAL);

    conv_x_kernel<<<BATCH, 256>>>(x);
    conv_loc_kernel<<<CDIM, 256>>>(loc);
    invs_kernel<<<(CDIM + 255) / 256, 256>>>(scale);

    dim3 grid(NBT, NCT);
    rbf_main_kernel<<<grid, 256, SMEM_TOTAL>>>(w);

    reduce_out_kernel<<<(BATCH * ODIM + 255) / 256, 256>>>(out);
}